// round 1
// baseline (speedup 1.0000x reference)
#include <cuda_runtime.h>
#include <math.h>

// Problem constants
#define BB 8
#define CC 64
#define HH 128
#define WW 128
#define OO 64
#define HWSZ (HH*WW)

// Scratch (static __device__, allowed)
__device__ float g_off [BB*18*HH*WW];   // conv output, channels 0..17 (dy0,dx0,dy1,dx1,...)
__device__ float g_mask[BB* 9*HH*WW];   // sigmoid(conv) channels
__device__ float g_wre [9*64*64];       // w_dcn transposed: [k][c][o]
__device__ float g_wconv[64*9*28];      // conv weights packed: [(c*9+p)][oc(0..17=off,18..26=mask,27=pad)]

// ---------------------------------------------------------------------------
// Kernel C: weight reorder (runs once per launch, trivial cost)
// ---------------------------------------------------------------------------
__global__ void prep_kernel(const float* __restrict__ w_dcn,
                            const float* __restrict__ w_off,
                            const float* __restrict__ w_mask) {
    int i = blockIdx.x * 256 + threadIdx.x;
    const int N1 = 9*64*64;
    if (i < N1) {
        int k = i >> 12;            // 0..8
        int c = (i >> 6) & 63;
        int o = i & 63;
        g_wre[i] = w_dcn[(o*64 + c)*9 + k];
    }
    int j = i - N1;
    if (j >= 0 && j < 64*9*28) {
        int cp = j / 28;            // c*9+p
        int oc = j % 28;
        int c = cp / 9, p = cp % 9;
        float v = 0.f;
        if (oc < 18)      v = w_off [(oc*64 + c)*9 + p];
        else if (oc < 27) v = w_mask[((oc-18)*64 + c)*9 + p];
        g_wconv[j] = v;
    }
}

// ---------------------------------------------------------------------------
// Kernel A: 3x3 conv, 64 -> 27 channels (18 offset + 9 mask w/ sigmoid)
// Tile: 16 rows x 32 cols per block; 256 threads, each thread 2 pixels.
// ---------------------------------------------------------------------------
__global__ __launch_bounds__(256) void conv_kernel(const float* __restrict__ x,
                                                   const float* __restrict__ b_off,
                                                   const float* __restrict__ b_mask) {
    __shared__ float s_x[8][18][34];     // 8 channels, 18 rows (16+halo), 34 cols (32+halo)
    __shared__ float s_w[72][28];        // 8 channels * 9 taps, 28 (27 oc + pad)

    const int tid = threadIdx.x;
    const int b  = blockIdx.z;
    const int h0 = blockIdx.y * 16;
    const int x0 = blockIdx.x * 32;
    const int ty = tid >> 4;             // 0..15
    const int tx = tid & 15;             // 0..15 ; pixels at cols tx and tx+16

    float acc0[28], acc1[28];
    #pragma unroll
    for (int i = 0; i < 28; i++) { acc0[i] = 0.f; acc1[i] = 0.f; }

    for (int cc = 0; cc < 8; cc++) {
        __syncthreads();
        // load 8-channel x tile with zero halo
        for (int i = tid; i < 8*18*34; i += 256) {
            int c   = i / (18*34);
            int r   = (i / 34) % 18;
            int col = i % 34;
            int gy = h0 + r - 1;
            int gx = x0 + col - 1;
            float v = 0.f;
            if (gy >= 0 && gy < HH && gx >= 0 && gx < WW)
                v = x[(((b*CC) + cc*8 + c)*HH + gy)*WW + gx];
            s_x[c][r][col] = v;
        }
        // load packed conv weights for this channel chunk (coalesced)
        for (int i = tid; i < 72*28; i += 256)
            (&s_w[0][0])[i] = g_wconv[cc*72*28 + i];
        __syncthreads();

        #pragma unroll 1
        for (int c = 0; c < 8; c++) {
            #pragma unroll
            for (int p = 0; p < 9; p++) {
                const int di = p / 3, dj = p % 3;
                float xv0 = s_x[c][ty + di][tx + dj];
                float xv1 = s_x[c][ty + di][tx + 16 + dj];
                const float4* wr = (const float4*)(&s_w[c*9 + p][0]);
                #pragma unroll
                for (int q = 0; q < 7; q++) {
                    float4 wv = wr[q];
                    acc0[q*4+0] += xv0 * wv.x;  acc1[q*4+0] += xv1 * wv.x;
                    acc0[q*4+1] += xv0 * wv.y;  acc1[q*4+1] += xv1 * wv.y;
                    acc0[q*4+2] += xv0 * wv.z;  acc1[q*4+2] += xv1 * wv.z;
                    acc0[q*4+3] += xv0 * wv.w;  acc1[q*4+3] += xv1 * wv.w;
                }
            }
        }
    }

    const int h  = h0 + ty;
    const int wA = x0 + tx;
    const int wB = wA + 16;
    #pragma unroll
    for (int oc = 0; oc < 18; oc++) {
        float bb = b_off[oc];
        g_off[((b*18 + oc)*HH + h)*WW + wA] = acc0[oc] + bb;
        g_off[((b*18 + oc)*HH + h)*WW + wB] = acc1[oc] + bb;
    }
    #pragma unroll
    for (int oc = 0; oc < 9; oc++) {
        float bb = b_mask[oc];
        float vA = acc0[18 + oc] + bb;
        float vB = acc1[18 + oc] + bb;
        g_mask[((b*9 + oc)*HH + h)*WW + wA] = 1.f / (1.f + expf(-vA));
        g_mask[((b*9 + oc)*HH + h)*WW + wB] = 1.f / (1.f + expf(-vB));
    }
}

// ---------------------------------------------------------------------------
// Kernel B: fused bilinear sampling + per-pixel GEMM (out = W_dcn * sampled + b)
// One block = one (b, h, 64-pixel w segment). 256 threads.
// Per k: coords (64 threads) -> sample 64px x 64ch -> 64x64x64 GEMM accumulate.
// ---------------------------------------------------------------------------
__global__ __launch_bounds__(256) void dcn_kernel(const float* __restrict__ x,
                                                  const float* __restrict__ b_dcn,
                                                  float* __restrict__ out) {
    __shared__ float s_w[64*64];        // [c][o]  for current k
    __shared__ float s_samp[64*64];     // [c][p]
    __shared__ int   s_addr[4][64];
    __shared__ float s_wt[4][64];

    const int tid  = threadIdx.x;
    const int bid  = blockIdx.x;
    const int wseg = bid & 1;
    const int h    = (bid >> 1) & 127;
    const int b    = bid >> 8;
    const int w0   = wseg * 64;

    // GEMM micro-tile: 4 pixels x 4 outputs
    const int pg = tid & 15, og = tid >> 4;
    const int p0 = pg * 4,  o0 = og * 4;
    // sampling mapping
    const int sp = tid & 63, cb = tid >> 6;   // pixel, channel-group (16 ch each)

    float acc[4][4];
    #pragma unroll
    for (int i = 0; i < 4; i++)
        #pragma unroll
        for (int j = 0; j < 4; j++) acc[i][j] = 0.f;

    for (int k = 0; k < 9; k++) {
        __syncthreads();   // protect smem reuse from previous iteration

        if (tid < 64) {
            const int p = tid;
            const int w = w0 + p;
            float dy = g_off[((b*18 + 2*k    )*HH + h)*WW + w];
            float dx = g_off[((b*18 + 2*k + 1)*HH + h)*WW + w];
            float m  = g_mask[((b*9 + k)*HH + h)*WW + w];
            float py = (float)(h - 1 + k/3) + dy;
            float px = (float)(w - 1 + k%3) + dx;
            float y0f = floorf(py), x0f = floorf(px);
            float fy = py - y0f,  fx = px - x0f;
            int y0 = (int)y0f, xx0 = (int)x0f;
            int y1 = y0 + 1,   xx1 = xx0 + 1;
            float vy0 = (y0  >= 0 && y0  <= HH-1) ? 1.f : 0.f;
            float vy1 = (y1  >= 0 && y1  <= HH-1) ? 1.f : 0.f;
            float vx0 = (xx0 >= 0 && xx0 <= WW-1) ? 1.f : 0.f;
            float vx1 = (xx1 >= 0 && xx1 <= WW-1) ? 1.f : 0.f;
            int y0c = min(max(y0, 0), HH-1), y1c = min(max(y1, 0), HH-1);
            int x0c = min(max(xx0, 0), WW-1), x1c = min(max(xx1, 0), WW-1);
            s_addr[0][p] = y0c*WW + x0c;  s_wt[0][p] = (1.f-fy)*(1.f-fx)*vy0*vx0*m;
            s_addr[1][p] = y0c*WW + x1c;  s_wt[1][p] = (1.f-fy)*fx      *vy0*vx1*m;
            s_addr[2][p] = y1c*WW + x0c;  s_wt[2][p] = fy*(1.f-fx)      *vy1*vx0*m;
            s_addr[3][p] = y1c*WW + x1c;  s_wt[3][p] = fy*fx            *vy1*vx1*m;
        }
        // load transposed w_dcn slice for this k (contiguous copy, coalesced)
        #pragma unroll
        for (int n = 0; n < 16; n++)
            s_w[n*256 + tid] = g_wre[k*4096 + n*256 + tid];
        __syncthreads();

        // sampling: each thread handles 16 channels of one pixel
        {
            int a0 = s_addr[0][sp], a1 = s_addr[1][sp], a2 = s_addr[2][sp], a3 = s_addr[3][sp];
            float q0 = s_wt[0][sp], q1 = s_wt[1][sp], q2 = s_wt[2][sp], q3 = s_wt[3][sp];
            const float* xb = x + (size_t)(b*CC + cb*16) * HWSZ;
            #pragma unroll
            for (int j = 0; j < 16; j++) {
                const float* xc = xb + (size_t)j * HWSZ;
                float v = q0*xc[a0] + q1*xc[a1] + q2*xc[a2] + q3*xc[a3];
                s_samp[(cb*16 + j)*64 + sp] = v;
            }
        }
        __syncthreads();

        // GEMM accumulate: acc[o][p] += sum_c samp[c][p] * w[c][o]
        #pragma unroll 4
        for (int c = 0; c < 64; c++) {
            float4 sv = *(const float4*)&s_samp[c*64 + p0];
            float4 wv = *(const float4*)&s_w  [c*64 + o0];
            acc[0][0] += wv.x*sv.x; acc[0][1] += wv.x*sv.y; acc[0][2] += wv.x*sv.z; acc[0][3] += wv.x*sv.w;
            acc[1][0] += wv.y*sv.x; acc[1][1] += wv.y*sv.y; acc[1][2] += wv.y*sv.z; acc[1][3] += wv.y*sv.w;
            acc[2][0] += wv.z*sv.x; acc[2][1] += wv.z*sv.y; acc[2][2] += wv.z*sv.z; acc[2][3] += wv.z*sv.w;
            acc[3][0] += wv.w*sv.x; acc[3][1] += wv.w*sv.y; acc[3][2] += wv.w*sv.z; acc[3][3] += wv.w*sv.w;
        }
    }

    #pragma unroll
    for (int jo = 0; jo < 4; jo++) {
        float bb = b_dcn[o0 + jo];
        float4 r = make_float4(acc[jo][0] + bb, acc[jo][1] + bb,
                               acc[jo][2] + bb, acc[jo][3] + bb);
        *(float4*)&out[((size_t)(b*OO + o0 + jo)*HH + h)*WW + w0 + p0] = r;
    }
}

// ---------------------------------------------------------------------------
extern "C" void kernel_launch(void* const* d_in, const int* in_sizes, int n_in,
                              void* d_out, int out_size) {
    const float* x      = (const float*)d_in[0];
    const float* w_off  = (const float*)d_in[1];
    const float* b_off  = (const float*)d_in[2];
    const float* w_mask = (const float*)d_in[3];
    const float* b_mask = (const float*)d_in[4];
    const float* w_dcn  = (const float*)d_in[5];
    const float* b_dcn  = (const float*)d_in[6];
    float* out = (float*)d_out;

    int prep_n = 9*64*64 + 64*9*28;
    prep_kernel<<<(prep_n + 255)/256, 256>>>(w_dcn, w_off, w_mask);
    conv_kernel<<<dim3(WW/32, HH/16, BB), 256>>>(x, b_off, b_mask);
    dcn_kernel<<<BB * HH * (WW/64), 256>>>(x, b_dcn, out);
}

// round 2
// speedup vs baseline: 1.0492x; 1.0492x over previous
#include <cuda_runtime.h>
#include <math.h>

#define BB 8
#define CC 64
#define HH 128
#define WW 128
#define OO 64
#define HWSZ (HH*WW)

typedef unsigned long long u64;

__device__ float g_off [BB*18*HH*WW];
__device__ float g_mask[BB* 9*HH*WW];
__device__ float g_wre [9*64*64];      // w_dcn transposed: [k][c][o]
__device__ float g_wconv[64*9*28];     // [(c*9+p)][28] : 0..17 off, 18..26 mask, 27 pad

// ---- f32x2 packed helpers -------------------------------------------------
__device__ __forceinline__ u64 pk2(float a, float b) {
    u64 r; asm("mov.b64 %0, {%1,%2};" : "=l"(r) : "f"(a), "f"(b)); return r;
}
__device__ __forceinline__ void fma2(u64& d, u64 a, u64 b) {
    asm("fma.rn.f32x2 %0, %1, %2, %0;" : "+l"(d) : "l"(a), "l"(b));
}
__device__ __forceinline__ u64 add2(u64 a, u64 b) {
    u64 r; asm("add.rn.f32x2 %0, %1, %2;" : "=l"(r) : "l"(a), "l"(b)); return r;
}
__device__ __forceinline__ float2 upk2(u64 v) {
    float2 r; asm("mov.b64 {%0,%1}, %2;" : "=f"(r.x), "=f"(r.y) : "l"(v)); return r;
}

// ---------------------------------------------------------------------------
// prep: weight reorders (trivial)
// ---------------------------------------------------------------------------
__global__ void prep_kernel(const float* __restrict__ w_dcn,
                            const float* __restrict__ w_off,
                            const float* __restrict__ w_mask) {
    int i = blockIdx.x * 256 + threadIdx.x;
    const int N1 = 9*64*64;
    if (i < N1) {
        int k = i >> 12, c = (i >> 6) & 63, o = i & 63;
        g_wre[i] = w_dcn[(o*64 + c)*9 + k];
    }
    int j = i - N1;
    if (j >= 0 && j < 64*9*28) {
        int cp = j / 28, oc = j % 28;
        int c = cp / 9, p = cp % 9;
        float v = 0.f;
        if (oc < 18)      v = w_off [(oc*64 + c)*9 + p];
        else if (oc < 27) v = w_mask[((oc-18)*64 + c)*9 + p];
        g_wconv[j] = v;
    }
}

// ---------------------------------------------------------------------------
// conv: 3x3, 64 -> 27 ch.  Tile 32x32, 256 thr.
// thread = 8 consecutive px (one row) x 14 oc (7 pairs).  FFMA2 inner.
// ---------------------------------------------------------------------------
__global__ __launch_bounds__(256) void conv_kernel(const float* __restrict__ x,
                                                   const float* __restrict__ b_off,
                                                   const float* __restrict__ b_mask) {
    __shared__ float s_x[8][34][34];   // 37.0 KB
    __shared__ float s_w[72][32];      //  9.2 KB  (half0: cols 0..13, half1: cols 16..29)

    const int tid = threadIdx.x;
    const int b  = blockIdx.z;
    const int h0 = blockIdx.y * 32;
    const int x0 = blockIdx.x * 32;

    const int ochalf = tid >> 7;          // 0/1
    const int pos    = tid & 127;
    const int row    = pos >> 2;          // 0..31
    const int col0   = (pos & 3) * 8;     // 0,8,16,24
    const int wcolix = ochalf * 16;       // s_w column base
    const int ocbase = ochalf * 14;       // logical oc base

    u64 acc[7][8];
    #pragma unroll
    for (int a = 0; a < 7; a++)
        #pragma unroll
        for (int j = 0; j < 8; j++) acc[a][j] = 0ull;

    for (int cc = 0; cc < 8; cc++) {
        __syncthreads();
        // x tile (8 ch, halo)
        for (int i = tid; i < 8*34*34; i += 256) {
            int c = i / 1156, rem = i % 1156;
            int r = rem / 34, col = rem % 34;
            int gy = h0 + r - 1, gx = x0 + col - 1;
            float v = 0.f;
            if (gy >= 0 && gy < HH && gx >= 0 && gx < WW)
                v = x[(((b*CC) + cc*8 + c)*HH + gy)*WW + gx];
            s_x[c][r][col] = v;
        }
        // padded weight tile
        for (int i = tid; i < 72*32; i += 256) {
            int r = i >> 5, jj = i & 31;
            float v = 0.f;
            int ocj = (jj < 14) ? jj : (jj >= 16 && jj < 30) ? (jj - 2) : -1;
            if (ocj >= 0) v = g_wconv[(cc*72 + r)*28 + ocj];
            s_w[r][jj] = v;
        }
        __syncthreads();

        #pragma unroll 1
        for (int c = 0; c < 8; c++) {
            #pragma unroll
            for (int di = 0; di < 3; di++) {
                u64 wpk[10];
                #pragma unroll
                for (int j = 0; j < 10; j++) {
                    float t = s_x[c][row + di][col0 + j];
                    wpk[j] = pk2(t, t);
                }
                #pragma unroll
                for (int dj = 0; dj < 3; dj++) {
                    const u64* wp = (const u64*)&s_w[c*9 + di*3 + dj][wcolix];
                    #pragma unroll
                    for (int op = 0; op < 7; op++) {
                        u64 wv = wp[op];
                        #pragma unroll
                        for (int j = 0; j < 8; j++) fma2(acc[op][j], wv, wpk[j + dj]);
                    }
                }
            }
        }
    }

    const int h  = h0 + row;
    const int wc = x0 + col0;
    #pragma unroll
    for (int op = 0; op < 7; op++) {
        float vlo[8], vhi[8];
        #pragma unroll
        for (int j = 0; j < 8; j++) {
            float2 t = upk2(acc[op][j]);
            vlo[j] = t.x; vhi[j] = t.y;
        }
        #pragma unroll
        for (int half = 0; half < 2; half++) {
            int oc = ocbase + 2*op + half;
            if (oc >= 27) continue;
            float* vv = half ? vhi : vlo;
            if (oc < 18) {
                float bb = b_off[oc];
                float* dst = &g_off[((b*18 + oc)*HH + h)*WW + wc];
                *(float4*)&dst[0] = make_float4(vv[0]+bb, vv[1]+bb, vv[2]+bb, vv[3]+bb);
                *(float4*)&dst[4] = make_float4(vv[4]+bb, vv[5]+bb, vv[6]+bb, vv[7]+bb);
            } else {
                float bb = b_mask[oc - 18];
                float* dst = &g_mask[((b*9 + oc - 18)*HH + h)*WW + wc];
                float s[8];
                #pragma unroll
                for (int j = 0; j < 8; j++) s[j] = 1.f / (1.f + expf(-(vv[j]+bb)));
                *(float4*)&dst[0] = make_float4(s[0], s[1], s[2], s[3]);
                *(float4*)&dst[4] = make_float4(s[4], s[5], s[6], s[7]);
            }
        }
    }
}

// ---------------------------------------------------------------------------
// dcn: fused bilinear sample + GEMM.  Block = (b, 2 rows) = 256 px x 64 o.
// Channels processed in two 32-ch passes (static smem <= 48KB).
// Thread GEMM tile: 8 px (4 f32x2 pairs) x 8 o.  FFMA2 inner.
// ---------------------------------------------------------------------------
__global__ __launch_bounds__(256) void dcn_kernel(const float* __restrict__ x,
                                                  const float* __restrict__ b_dcn,
                                                  float* __restrict__ out) {
    __shared__ float s_samp[32*256];   // 32 KB  [cl][px]
    __shared__ float s_w[32*64];       //  8 KB  [cl][o]

    const int tid = threadIdx.x;
    const int b   = blockIdx.x >> 6;
    const int h0  = (blockIdx.x & 63) << 1;

    // sampling: this thread owns pixel sp
    const int sp   = tid;
    const int srow = sp >> 7, scol = sp & 127;
    const int sh   = h0 + srow;

    // GEMM tile
    const int p0 = (tid & 31) * 8;     // 8 px
    const int o0 = (tid >> 5) * 8;     // 8 o   (warp-uniform -> smem broadcast)

    u64 acc[8][4];
    #pragma unroll
    for (int o = 0; o < 8; o++)
        #pragma unroll
        for (int p = 0; p < 4; p++) acc[o][p] = 0ull;

    const float* xb = x + (size_t)b * CC * HWSZ;

    for (int k = 0; k < 9; k++) {
        // per-pixel coords (registers only)
        float dy = g_off[((b*18 + 2*k    )*HH + sh)*WW + scol];
        float dx = g_off[((b*18 + 2*k + 1)*HH + sh)*WW + scol];
        float m  = g_mask[((b*9 + k)*HH + sh)*WW + scol];
        float py = (float)(sh - 1 + k/3) + dy;
        float px = (float)(scol - 1 + k%3) + dx;
        float y0f = floorf(py), x0f = floorf(px);
        float fy = py - y0f, fx = px - x0f;
        int y0 = (int)y0f, xx0 = (int)x0f;
        int y1 = y0 + 1,  xx1 = xx0 + 1;
        float vy0 = (y0  >= 0 && y0  < HH) ? 1.f : 0.f;
        float vy1 = (y1  >= 0 && y1  < HH) ? 1.f : 0.f;
        float vx0 = (xx0 >= 0 && xx0 < WW) ? 1.f : 0.f;
        float vx1 = (xx1 >= 0 && xx1 < WW) ? 1.f : 0.f;
        int y0c = min(max(y0, 0), HH-1), y1c = min(max(y1, 0), HH-1);
        int x0c = min(max(xx0, 0), WW-1), x1c = min(max(xx1, 0), WW-1);
        int a0 = y0c*WW + x0c, a1 = y0c*WW + x1c;
        int a2 = y1c*WW + x0c, a3 = y1c*WW + x1c;
        float q0 = (1.f-fy)*(1.f-fx)*vy0*vx0*m;
        float q1 = (1.f-fy)*fx      *vy0*vx1*m;
        float q2 = fy*(1.f-fx)      *vy1*vx0*m;
        float q3 = fy*fx            *vy1*vx1*m;

        #pragma unroll 1
        for (int half = 0; half < 2; half++) {
            __syncthreads();   // previous GEMM pass done reading smem
            // weight slice [32 c][64 o]
            #pragma unroll
            for (int n = 0; n < 8; n++)
                s_w[n*256 + tid] = g_wre[k*4096 + half*2048 + n*256 + tid];
            // sample 32 channels of own pixel
            const float* xh = xb + (size_t)(half*32) * HWSZ;
            #pragma unroll 4
            for (int cl = 0; cl < 32; cl++) {
                const float* xc = xh + (size_t)cl * HWSZ;
                float v = q0*xc[a0] + q1*xc[a1] + q2*xc[a2] + q3*xc[a3];
                s_samp[cl*256 + sp] = v;
            }
            __syncthreads();
            // GEMM accumulate
            #pragma unroll 4
            for (int cl = 0; cl < 32; cl++) {
                const ulonglong2* sv = (const ulonglong2*)&s_samp[cl*256 + p0];
                ulonglong2 sA = sv[0];         // pairs (p0,p1) (p2,p3)
                ulonglong2 sB = sv[1];         // pairs (p4,p5) (p6,p7)
                float4 w0 = *(const float4*)&s_w[cl*64 + o0];
                float4 w1 = *(const float4*)&s_w[cl*64 + o0 + 4];
                u64 wb;
                wb = pk2(w0.x, w0.x); fma2(acc[0][0], wb, sA.x); fma2(acc[0][1], wb, sA.y); fma2(acc[0][2], wb, sB.x); fma2(acc[0][3], wb, sB.y);
                wb = pk2(w0.y, w0.y); fma2(acc[1][0], wb, sA.x); fma2(acc[1][1], wb, sA.y); fma2(acc[1][2], wb, sB.x); fma2(acc[1][3], wb, sB.y);
                wb = pk2(w0.z, w0.z); fma2(acc[2][0], wb, sA.x); fma2(acc[2][1], wb, sA.y); fma2(acc[2][2], wb, sB.x); fma2(acc[2][3], wb, sB.y);
                wb = pk2(w0.w, w0.w); fma2(acc[3][0], wb, sA.x); fma2(acc[3][1], wb, sA.y); fma2(acc[3][2], wb, sB.x); fma2(acc[3][3], wb, sB.y);
                wb = pk2(w1.x, w1.x); fma2(acc[4][0], wb, sA.x); fma2(acc[4][1], wb, sA.y); fma2(acc[4][2], wb, sB.x); fma2(acc[4][3], wb, sB.y);
                wb = pk2(w1.y, w1.y); fma2(acc[5][0], wb, sA.x); fma2(acc[5][1], wb, sA.y); fma2(acc[5][2], wb, sB.x); fma2(acc[5][3], wb, sB.y);
                wb = pk2(w1.z, w1.z); fma2(acc[6][0], wb, sA.x); fma2(acc[6][1], wb, sA.y); fma2(acc[6][2], wb, sB.x); fma2(acc[6][3], wb, sB.y);
                wb = pk2(w1.w, w1.w); fma2(acc[7][0], wb, sA.x); fma2(acc[7][1], wb, sA.y); fma2(acc[7][2], wb, sB.x); fma2(acc[7][3], wb, sB.y);
            }
        }
    }

    // epilogue
    const int prow = p0 >> 7, pcol = p0 & 127;
    const int oh = h0 + prow;
    #pragma unroll
    for (int o = 0; o < 8; o++) {
        float bb = b_dcn[o0 + o];
        u64 bp = pk2(bb, bb);
        u64 r0 = add2(acc[o][0], bp), r1 = add2(acc[o][1], bp);
        u64 r2 = add2(acc[o][2], bp), r3 = add2(acc[o][3], bp);
        float* dst = &out[((size_t)(b*OO + o0 + o)*HH + oh)*WW + pcol];
        ulonglong2 v0; v0.x = r0; v0.y = r1;
        ulonglong2 v1; v1.x = r2; v1.y = r3;
        ((ulonglong2*)dst)[0] = v0;
        ((ulonglong2*)dst)[1] = v1;
    }
}

// ---------------------------------------------------------------------------
extern "C" void kernel_launch(void* const* d_in, const int* in_sizes, int n_in,
                              void* d_out, int out_size) {
    const float* x      = (const float*)d_in[0];
    const float* w_off  = (const float*)d_in[1];
    const float* b_off  = (const float*)d_in[2];
    const float* w_mask = (const float*)d_in[3];
    const float* b_mask = (const float*)d_in[4];
    const float* w_dcn  = (const float*)d_in[5];
    const float* b_dcn  = (const float*)d_in[6];
    float* out = (float*)d_out;

    int prep_n = 9*64*64 + 64*9*28;
    prep_kernel<<<(prep_n + 255)/256, 256>>>(w_dcn, w_off, w_mask);
    conv_kernel<<<dim3(WW/32, HH/32, BB), 256>>>(x, b_off, b_mask);
    dcn_kernel<<<BB * (HH/2), 256>>>(x, b_dcn, out);
}